// round 1
// baseline (speedup 1.0000x reference)
#include <cuda_runtime.h>

// Problem constants: B=8, T=1024, F=512, H=8, D=64, P=2047
#define GN 512
#define GK 512

// Scratch (static __device__ arrays — no allocation allowed)
__device__ float g_qu[8 * 8 * 1024 * 64];   // [B,H,T,D] (q + pos_bias_u) * scale
__device__ float g_qv[8 * 8 * 1024 * 64];   // [B,H,T,D] (q + pos_bias_v) * scale
__device__ float g_k [8 * 8 * 1024 * 64];   // [B,H,T,D]
__device__ float g_v [8 * 8 * 1024 * 64];   // [B,H,T,D]
__device__ float g_p [8 * 2047 * 64];       // [H,P,D]
__device__ float g_att[8 * 1024 * 8 * 64];  // [B,T,H,D] = [B*T, F]

// ---------------------------------------------------------------------------
// Tiled NT SGEMM: C[m,n] = sum_k A[m,k] * W[n,k] (+ bias terms), N=K=512.
// 128x128 block tile, 256 threads, 8x8 microtile, BK=16.
// mode 0: out1[m*512+n] = acc + bias[n]                       (final proj)
// mode 1: out1[BHTD]    = acc + bias[n]                       (k, v)
// mode 2: out1[BHTD] = (acc+bias+bu)*scale, out2 = (acc+bias+bv)*scale (q)
// mode 3: out1[(h*2047+m)*64+d] = acc                         (pos proj)
// ---------------------------------------------------------------------------
__global__ __launch_bounds__(256) void gemm_nt(
    const float* __restrict__ A, const float* __restrict__ W,
    const float* __restrict__ bias, const float* __restrict__ bu,
    const float* __restrict__ bv,
    float* __restrict__ out1, float* __restrict__ out2,
    int M, int mode, float scale)
{
    __shared__ float As[16][128];
    __shared__ float Ws[16][128];

    const int tid = threadIdx.x;
    const int m0 = blockIdx.y * 128;
    const int n0 = blockIdx.x * 128;
    const int tm = (tid >> 4) << 3;   // 0..120 step 8
    const int tn = (tid & 15) << 3;   // 0..120 step 8

    float acc[8][8];
#pragma unroll
    for (int i = 0; i < 8; i++)
#pragma unroll
        for (int j = 0; j < 8; j++) acc[i][j] = 0.f;

    for (int k0 = 0; k0 < GK; k0 += 16) {
#pragma unroll
        for (int q = 0; q < 2; q++) {
            int flat = tid * 2 + q;          // 0..511
            int mm = flat >> 2;              // 0..127
            int kk = (flat & 3) << 2;        // 0,4,8,12
            float4 av = make_float4(0.f, 0.f, 0.f, 0.f);
            int gm = m0 + mm;
            if (gm < M)
                av = *(const float4*)(A + (size_t)gm * GK + k0 + kk);
            As[kk + 0][mm] = av.x; As[kk + 1][mm] = av.y;
            As[kk + 2][mm] = av.z; As[kk + 3][mm] = av.w;
            float4 wv = *(const float4*)(W + (size_t)(n0 + mm) * GK + k0 + kk);
            Ws[kk + 0][mm] = wv.x; Ws[kk + 1][mm] = wv.y;
            Ws[kk + 2][mm] = wv.z; Ws[kk + 3][mm] = wv.w;
        }
        __syncthreads();
#pragma unroll
        for (int k = 0; k < 16; k++) {
            float a[8], w[8];
            *(float4*)(a)     = *(const float4*)&As[k][tm];
            *(float4*)(a + 4) = *(const float4*)&As[k][tm + 4];
            *(float4*)(w)     = *(const float4*)&Ws[k][tn];
            *(float4*)(w + 4) = *(const float4*)&Ws[k][tn + 4];
#pragma unroll
            for (int i = 0; i < 8; i++)
#pragma unroll
                for (int j = 0; j < 8; j++)
                    acc[i][j] = fmaf(a[i], w[j], acc[i][j]);
        }
        __syncthreads();
    }

#pragma unroll
    for (int i = 0; i < 8; i++) {
        int m = m0 + tm + i;
        if (m >= M) continue;
#pragma unroll
        for (int j = 0; j < 8; j++) {
            int n = n0 + tn + j;
            float v = acc[i][j];
            if (mode == 0) {
                out1[(size_t)m * GN + n] = v + bias[n];
            } else if (mode == 1) {
                int b = m >> 10, t = m & 1023, h = n >> 6, d = n & 63;
                out1[(((size_t)(b * 8 + h) << 10) + t) * 64 + d] = v + bias[n];
            } else if (mode == 2) {
                int b = m >> 10, t = m & 1023, h = n >> 6, d = n & 63;
                size_t idx = (((size_t)(b * 8 + h) << 10) + t) * 64 + d;
                float base = v + bias[n];
                out1[idx] = (base + bu[n]) * scale;
                out2[idx] = (base + bv[n]) * scale;
            } else { // mode 3
                int h = n >> 6, d = n & 63;
                out1[((size_t)h * 2047 + m) * 64 + d] = v;
            }
        }
    }
}

// ---------------------------------------------------------------------------
// Flash attention with relative-position bias via banded index remap:
//   scores[i,j] = qu[i]·k[j] + qv[i]·p[1023 + j - i]   (scale pre-folded)
// Block: 64 queries for one (b,h). 16 key tiles of 64. Online softmax.
// Thread layout 16x16, each thread owns 4 rows x 4 cols.
// ---------------------------------------------------------------------------
#define SMEM_FLOATS (4 * 64 * 65 + 127 * 65)
#define SMEM_BYTES  (SMEM_FLOATS * 4)

__global__ __launch_bounds__(256) void attn_kernel(
    const float* __restrict__ qu, const float* __restrict__ qv,
    const float* __restrict__ kk, const float* __restrict__ vv,
    const float* __restrict__ pp, float* __restrict__ att)
{
    extern __shared__ float sm[];
    float (*qu_s)[65] = (float (*)[65])(sm);
    float (*qv_s)[65] = (float (*)[65])(sm + 64 * 65);
    float (*kp_s)[65] = (float (*)[65])(sm + 2 * 64 * 65);  // K tile, then exp(P) tile
    float (*v_s)[65]  = (float (*)[65])(sm + 3 * 64 * 65);
    float (*p_s)[65]  = (float (*)[65])(sm + 4 * 64 * 65);  // 127 rows

    const int tid = threadIdx.x;
    const int tx = tid & 15, ty = tid >> 4;
    const int i0 = blockIdx.x << 6;
    const int bh = blockIdx.y;
    const int h = bh & 7, b = bh >> 3;

    // Load query tiles once
    for (int idx = tid; idx < 64 * 64; idx += 256) {
        int r = idx >> 6, c = idx & 63;
        size_t g = ((size_t)bh * 1024 + i0 + r) * 64 + c;
        qu_s[r][c] = qu[g];
        qv_s[r][c] = qv[g];
    }

    float m_i[4], l_i[4], acc[4][4];
#pragma unroll
    for (int i = 0; i < 4; i++) {
        m_i[i] = -1e30f;
        l_i[i] = 0.f;
#pragma unroll
        for (int j = 0; j < 4; j++) acc[i][j] = 0.f;
    }

    const int pb = ((tx - ty) << 2) + 60;   // base row in p slab, in [0,120]

    for (int jt = 0; jt < 16; jt++) {
        const int j0 = jt << 6;
        __syncthreads();   // previous iteration done with shared buffers
        for (int idx = tid; idx < 64 * 64; idx += 256) {
            int r = idx >> 6, c = idx & 63;
            size_t g = ((size_t)bh * 1024 + j0 + r) * 64 + c;
            kp_s[r][c] = kk[g];
            v_s[r][c]  = vv[g];
        }
        const int rbase = 960 + j0 - i0;   // in [0, 1920]
        for (int idx = tid; idx < 127 * 64; idx += 256) {
            int r = idx >> 6, c = idx & 63;
            p_s[r][c] = pp[((size_t)h * 2047 + rbase + r) * 64 + c];
        }
        __syncthreads();

        // S = Qu·K^T + Qv·P_band^T
        float s[4][4];
#pragma unroll
        for (int i = 0; i < 4; i++)
#pragma unroll
            for (int j = 0; j < 4; j++) s[i][j] = 0.f;

#pragma unroll 2
        for (int d = 0; d < 64; d++) {
            float ru[4], rv[4], rk[4], rp[7];
#pragma unroll
            for (int i = 0; i < 4; i++) {
                ru[i] = qu_s[(ty << 2) + i][d];
                rv[i] = qv_s[(ty << 2) + i][d];
                rk[i] = kp_s[(tx << 2) + i][d];
            }
#pragma unroll
            for (int t = 0; t < 7; t++) rp[t] = p_s[pb + t][d];
#pragma unroll
            for (int i = 0; i < 4; i++)
#pragma unroll
                for (int j = 0; j < 4; j++)
                    s[i][j] += ru[i] * rk[j] + rv[i] * rp[j - i + 3];
        }

        // Online softmax update (rows replicated across 16 tx lanes)
        float pf[4][4];
#pragma unroll
        for (int i = 0; i < 4; i++) {
            float mx = fmaxf(fmaxf(s[i][0], s[i][1]), fmaxf(s[i][2], s[i][3]));
            mx = fmaxf(mx, __shfl_xor_sync(0xffffffffu, mx, 1));
            mx = fmaxf(mx, __shfl_xor_sync(0xffffffffu, mx, 2));
            mx = fmaxf(mx, __shfl_xor_sync(0xffffffffu, mx, 4));
            mx = fmaxf(mx, __shfl_xor_sync(0xffffffffu, mx, 8));
            float mn = fmaxf(m_i[i], mx);
            float al = __expf(m_i[i] - mn);
            float rs = 0.f;
#pragma unroll
            for (int j = 0; j < 4; j++) {
                pf[i][j] = __expf(s[i][j] - mn);
                rs += pf[i][j];
            }
            rs += __shfl_xor_sync(0xffffffffu, rs, 1);
            rs += __shfl_xor_sync(0xffffffffu, rs, 2);
            rs += __shfl_xor_sync(0xffffffffu, rs, 4);
            rs += __shfl_xor_sync(0xffffffffu, rs, 8);
            l_i[i] = l_i[i] * al + rs;
            m_i[i] = mn;
#pragma unroll
            for (int j = 0; j < 4; j++) acc[i][j] *= al;
        }

        __syncthreads();   // everyone done reading K from kp_s
#pragma unroll
        for (int i = 0; i < 4; i++)
#pragma unroll
            for (int j = 0; j < 4; j++)
                kp_s[(ty << 2) + i][(tx << 2) + j] = pf[i][j];
        __syncthreads();

        // acc += P_tile @ V_tile
#pragma unroll 4
        for (int j = 0; j < 64; j++) {
            float pv[4], rv4[4];
#pragma unroll
            for (int i = 0; i < 4; i++) pv[i] = kp_s[(ty << 2) + i][j];
#pragma unroll
            for (int dd = 0; dd < 4; dd++) rv4[dd] = v_s[j][(tx << 2) + dd];
#pragma unroll
            for (int i = 0; i < 4; i++)
#pragma unroll
                for (int dd = 0; dd < 4; dd++)
                    acc[i][dd] = fmaf(pv[i], rv4[dd], acc[i][dd]);
        }
    }

    // Write normalized output: att[b, t, h, d]
#pragma unroll
    for (int i = 0; i < 4; i++) {
        int t = i0 + (ty << 2) + i;
        float inv = 1.f / l_i[i];
#pragma unroll
        for (int dd = 0; dd < 4; dd++)
            att[(((size_t)b * 1024 + t) * 8 + h) * 64 + (tx << 2) + dd] =
                acc[i][dd] * inv;
    }
}

// ---------------------------------------------------------------------------
extern "C" void kernel_launch(void* const* d_in, const int* in_sizes, int n_in,
                              void* d_out, int out_size)
{
    const float* query = (const float*)d_in[0];
    const float* key   = (const float*)d_in[1];
    const float* value = (const float*)d_in[2];
    const float* pos   = (const float*)d_in[3];
    const float* Wq    = (const float*)d_in[4];
    const float* bq    = (const float*)d_in[5];
    const float* Wk    = (const float*)d_in[6];
    const float* bk    = (const float*)d_in[7];
    const float* Wv    = (const float*)d_in[8];
    const float* bv_   = (const float*)d_in[9];
    const float* Wp    = (const float*)d_in[10];
    const float* Wo    = (const float*)d_in[11];
    const float* bo    = (const float*)d_in[12];
    const float* pbu   = (const float*)d_in[13];
    const float* pbv   = (const float*)d_in[14];

    float *qu_p, *qv_p, *k_p, *v_p, *p_p, *att_p;
    cudaGetSymbolAddress((void**)&qu_p,  g_qu);
    cudaGetSymbolAddress((void**)&qv_p,  g_qv);
    cudaGetSymbolAddress((void**)&k_p,   g_k);
    cudaGetSymbolAddress((void**)&v_p,   g_v);
    cudaGetSymbolAddress((void**)&p_p,   g_p);
    cudaGetSymbolAddress((void**)&att_p, g_att);

    cudaFuncSetAttribute(attn_kernel,
                         cudaFuncAttributeMaxDynamicSharedMemorySize,
                         SMEM_BYTES);

    dim3 thr(256);
    const float scale = 0.125f;   // 1/sqrt(64)

    // q projection (+pos_bias_u/v, scale folded), head-major outputs
    gemm_nt<<<dim3(4, 64), thr>>>(query, Wq, bq, pbu, pbv,
                                  qu_p, qv_p, 8192, 2, scale);
    // k, v projections
    gemm_nt<<<dim3(4, 64), thr>>>(key,   Wk, bk, nullptr, nullptr,
                                  k_p, nullptr, 8192, 1, 1.f);
    gemm_nt<<<dim3(4, 64), thr>>>(value, Wv, bv_, nullptr, nullptr,
                                  v_p, nullptr, 8192, 1, 1.f);
    // positional projection (no bias)
    gemm_nt<<<dim3(4, 16), thr>>>(pos,   Wp, nullptr, nullptr, nullptr,
                                  p_p, nullptr, 2047, 3, 1.f);
    // fused relative-position flash attention
    attn_kernel<<<dim3(16, 64), thr, SMEM_BYTES>>>(qu_p, qv_p, k_p, v_p, p_p,
                                                   att_p);
    // output projection -> d_out
    gemm_nt<<<dim3(4, 64), thr>>>(att_p, Wo, bo, nullptr, nullptr,
                                  (float*)d_out, nullptr, 8192, 0, 1.f);
}

// round 3
// speedup vs baseline: 2.0484x; 2.0484x over previous
#include <cuda_runtime.h>
#include <cstdint>

// Problem constants: B=8, T=1024, F=512, H=8, D=64, P=2047
// Scratch (static __device__ arrays — no allocation allowed)
__device__ float g_qu[8 * 8 * 1024 * 64];   // [B,H,T,D] (q + pos_bias_u) * scale
__device__ float g_qv[8 * 8 * 1024 * 64];   // [B,H,T,D] (q + pos_bias_v) * scale
__device__ float g_k [8 * 8 * 1024 * 64];   // [B,H,T,D]
__device__ float g_v [8 * 8 * 1024 * 64];   // [B,H,T,D]
__device__ float g_p [8 * 2047 * 64];       // [H,P,D]
__device__ float g_att[8 * 1024 * 512];     // [B*T, F]

__device__ __forceinline__ uint32_t f2tf(float x) {
    uint32_t r;
    asm("cvt.rna.tf32.f32 %0, %1;" : "=r"(r) : "f"(x));
    return r;
}

__device__ __forceinline__ void mma8(float c[4], const uint32_t a[4],
                                     uint32_t b0, uint32_t b1) {
    asm volatile(
        "mma.sync.aligned.m16n8k8.row.col.f32.tf32.tf32.f32 "
        "{%0,%1,%2,%3},{%4,%5,%6,%7},{%8,%9},{%0,%1,%2,%3};"
        : "+f"(c[0]), "+f"(c[1]), "+f"(c[2]), "+f"(c[3])
        : "r"(a[0]), "r"(a[1]), "r"(a[2]), "r"(a[3]), "r"(b0), "r"(b1));
}

// ---------------------------------------------------------------------------
// TF32 tensor-core NT GEMM: C[m,n] = sum_k A[m,k]*W[n,k] (+bias). N=K=512.
// Block 128x128, BK=32, 256 threads = 8 warps (4m x 2n), warp tile 32x64.
// mode 0: out1[m*512+n] = acc + bias[n]
// mode 1: out1[BHTD]    = acc + bias[n]
// mode 2: out1 = (acc+bias+bu)*scale, out2 = (acc+bias+bv)*scale  (BHTD)
// mode 3: out1[(h*2047+m)*64+d] = acc
// ---------------------------------------------------------------------------
#define WST 36
__global__ __launch_bounds__(256, 2) void gemm_mma(
    const float* __restrict__ A, const float* __restrict__ W,
    const float* __restrict__ bias, const float* __restrict__ bu,
    const float* __restrict__ bv,
    float* __restrict__ out1, float* __restrict__ out2,
    int M, int mode, float scale)
{
    __shared__ uint32_t As[128 * WST];
    __shared__ uint32_t Ws[128 * WST];

    const int tid = threadIdx.x;
    const int warp = tid >> 5, lane = tid & 31;
    const int gid = lane >> 2, tig = lane & 3;
    const int wm = warp & 3, wn = warp >> 2;
    const int m0 = blockIdx.y * 128, n0 = blockIdx.x * 128;

    float acc[2][8][4];
#pragma unroll
    for (int mt = 0; mt < 2; mt++)
#pragma unroll
        for (int nt = 0; nt < 8; nt++)
#pragma unroll
            for (int i = 0; i < 4; i++) acc[mt][nt][i] = 0.f;

    for (int k0 = 0; k0 < 512; k0 += 32) {
#pragma unroll
        for (int r = 0; r < 4; r++) {
            int idx = tid + r * 256;
            int row = idx >> 3, c4 = (idx & 7) << 2;
            float4 av = make_float4(0.f, 0.f, 0.f, 0.f);
            if (m0 + row < M)
                av = *(const float4*)(A + (size_t)(m0 + row) * 512 + k0 + c4);
            uint32_t* da = &As[row * WST + c4];
            da[0] = f2tf(av.x); da[1] = f2tf(av.y);
            da[2] = f2tf(av.z); da[3] = f2tf(av.w);
            float4 wv = *(const float4*)(W + (size_t)(n0 + row) * 512 + k0 + c4);
            uint32_t* dw = &Ws[row * WST + c4];
            dw[0] = f2tf(wv.x); dw[1] = f2tf(wv.y);
            dw[2] = f2tf(wv.z); dw[3] = f2tf(wv.w);
        }
        __syncthreads();
#pragma unroll
        for (int ks = 0; ks < 4; ks++) {
            uint32_t a[2][4];
#pragma unroll
            for (int mt = 0; mt < 2; mt++) {
                int rb = wm * 32 + mt * 16 + gid;
                int cb = ks * 8 + tig;
                a[mt][0] = As[rb * WST + cb];
                a[mt][1] = As[(rb + 8) * WST + cb];
                a[mt][2] = As[rb * WST + cb + 4];
                a[mt][3] = As[(rb + 8) * WST + cb + 4];
            }
#pragma unroll
            for (int nt = 0; nt < 8; nt++) {
                int nb = wn * 64 + nt * 8 + gid;
                uint32_t b0 = Ws[nb * WST + ks * 8 + tig];
                uint32_t b1 = Ws[nb * WST + ks * 8 + tig + 4];
                mma8(acc[0][nt], a[0], b0, b1);
                mma8(acc[1][nt], a[1], b0, b1);
            }
        }
        __syncthreads();
    }

#pragma unroll
    for (int mt = 0; mt < 2; mt++) {
#pragma unroll
        for (int hh = 0; hh < 2; hh++) {
            int m = m0 + wm * 32 + mt * 16 + gid + 8 * hh;
            if (m >= M) continue;
#pragma unroll
            for (int nt = 0; nt < 8; nt++) {
#pragma unroll
                for (int cc = 0; cc < 2; cc++) {
                    int n = n0 + wn * 64 + nt * 8 + 2 * tig + cc;
                    float v = acc[mt][nt][2 * hh + cc];
                    if (mode == 0) {
                        out1[(size_t)m * 512 + n] = v + bias[n];
                    } else if (mode == 1) {
                        int b = m >> 10, t = m & 1023, h = n >> 6, d = n & 63;
                        out1[(((size_t)(b * 8 + h) << 10) + t) * 64 + d] =
                            v + bias[n];
                    } else if (mode == 2) {
                        int b = m >> 10, t = m & 1023, h = n >> 6, d = n & 63;
                        size_t idx = (((size_t)(b * 8 + h) << 10) + t) * 64 + d;
                        float base = v + bias[n];
                        out1[idx] = (base + bu[n]) * scale;
                        out2[idx] = (base + bv[n]) * scale;
                    } else {
                        int h = n >> 6, d = n & 63;
                        out1[((size_t)h * 2047 + m) * 64 + d] = v;
                    }
                }
            }
        }
    }
}

// ---------------------------------------------------------------------------
// Tensor-core flash attention with relative positions.
// scores[i,j] = qu[i]·k[j] + E[i][63+j-i],  E = Qv·P_slab^T (mma GEMM).
// Block = 64 queries of one (b,h); 128 threads = 4 warps; warp owns 16 rows.
// ---------------------------------------------------------------------------
#define QST 68
#define EST 132
#define ATT_SMEM_U32 (4 * 64 * QST + 128 * QST + 64 * EST)
#define ATT_SMEM_BYTES (ATT_SMEM_U32 * 4)

__global__ __launch_bounds__(128) void attn_mma(
    const float* __restrict__ qu, const float* __restrict__ qv,
    const float* __restrict__ kk, const float* __restrict__ vv,
    const float* __restrict__ pp, float* __restrict__ att)
{
    extern __shared__ uint32_t sh[];
    uint32_t* Qu = sh;
    uint32_t* Qv = sh + 64 * QST;
    uint32_t* Ks = sh + 2 * 64 * QST;   // K tile; later reused for exp(S) tile
    uint32_t* Vs = sh + 3 * 64 * QST;
    uint32_t* Ps = sh + 4 * 64 * QST;   // 128 rows
    float*    Es = (float*)(sh + 4 * 64 * QST + 128 * QST);

    const int tid = threadIdx.x;
    const int w = tid >> 5, lane = tid & 31;
    const int gid = lane >> 2, tig = lane & 3;
    const int i0 = blockIdx.x << 6;
    const int bh = blockIdx.y;
    const int h = bh & 7, b = bh >> 3;

    // Load Q tiles (tf32)
#pragma unroll
    for (int r = 0; r < 8; r++) {
        int fi = tid + r * 128;
        int row = fi >> 4, c4 = (fi & 15) << 2;
        size_t g = ((size_t)bh * 1024 + i0 + row) * 64 + c4;
        float4 u = *(const float4*)(qu + g);
        float4 v = *(const float4*)(qv + g);
        uint32_t* du = &Qu[row * QST + c4];
        du[0] = f2tf(u.x); du[1] = f2tf(u.y); du[2] = f2tf(u.z); du[3] = f2tf(u.w);
        uint32_t* dv = &Qv[row * QST + c4];
        dv[0] = f2tf(v.x); dv[1] = f2tf(v.y); dv[2] = f2tf(v.z); dv[3] = f2tf(v.w);
    }
    __syncthreads();

    // Preload Q fragments for all 8 k-steps (held all kernel)
    uint32_t qua[8][4], qva[8][4];
#pragma unroll
    for (int ks = 0; ks < 8; ks++) {
        int rb = w * 16 + gid, cb = ks * 8 + tig;
        qua[ks][0] = Qu[rb * QST + cb];
        qua[ks][1] = Qu[(rb + 8) * QST + cb];
        qua[ks][2] = Qu[rb * QST + cb + 4];
        qua[ks][3] = Qu[(rb + 8) * QST + cb + 4];
        qva[ks][0] = Qv[rb * QST + cb];
        qva[ks][1] = Qv[(rb + 8) * QST + cb];
        qva[ks][2] = Qv[rb * QST + cb + 4];
        qva[ks][3] = Qv[(rb + 8) * QST + cb + 4];
    }

    float m_i[2] = {-1e30f, -1e30f}, l_i[2] = {0.f, 0.f};
    float oC[8][4];
#pragma unroll
    for (int nt = 0; nt < 8; nt++)
#pragma unroll
        for (int i = 0; i < 4; i++) oC[nt][i] = 0.f;

    for (int jt = 0; jt < 16; jt++) {
        const int j0 = jt << 6;
        __syncthreads();   // previous iteration fully done with smem tiles

        // Load K, V tiles
#pragma unroll
        for (int r = 0; r < 8; r++) {
            int fi = tid + r * 128;
            int row = fi >> 4, c4 = (fi & 15) << 2;
            size_t g = ((size_t)bh * 1024 + j0 + row) * 64 + c4;
            float4 kv = *(const float4*)(kk + g);
            float4 vf = *(const float4*)(vv + g);
            uint32_t* dk = &Ks[row * QST + c4];
            dk[0] = f2tf(kv.x); dk[1] = f2tf(kv.y);
            dk[2] = f2tf(kv.z); dk[3] = f2tf(kv.w);
            uint32_t* dv = &Vs[row * QST + c4];
            dv[0] = f2tf(vf.x); dv[1] = f2tf(vf.y);
            dv[2] = f2tf(vf.z); dv[3] = f2tf(vf.w);
        }
        // Load P slab: rows rbase..rbase+127 (row 127 only feeds unused E col)
        const int rbase = 960 + j0 - i0;
#pragma unroll
        for (int r = 0; r < 16; r++) {
            int fi = tid + r * 128;
            int row = fi >> 4, c4 = (fi & 15) << 2;
            int prow = rbase + row;
            prow = prow > 2046 ? 2046 : prow;
            float4 pv = *(const float4*)(pp + ((size_t)h * 2047 + prow) * 64 + c4);
            uint32_t* dp = &Ps[row * QST + c4];
            dp[0] = f2tf(pv.x); dp[1] = f2tf(pv.y);
            dp[2] = f2tf(pv.z); dp[3] = f2tf(pv.w);
        }
        __syncthreads();

        // E = Qv @ P_slab^T  (64 x 128), warp w writes its own 16 rows
#pragma unroll
        for (int nt = 0; nt < 16; nt++) {
            float e[4] = {0.f, 0.f, 0.f, 0.f};
#pragma unroll
            for (int ks = 0; ks < 8; ks++) {
                int rb = nt * 8 + gid, cb = ks * 8 + tig;
                mma8(e, qva[ks], Ps[rb * QST + cb], Ps[rb * QST + cb + 4]);
            }
            int er = w * 16 + gid, ec = nt * 8 + 2 * tig;
            Es[er * EST + ec] = e[0];
            Es[er * EST + ec + 1] = e[1];
            Es[(er + 8) * EST + ec] = e[2];
            Es[(er + 8) * EST + ec + 1] = e[3];
        }

        // S1 = Qu @ K^T (64 x 64)
        float sC[8][4];
#pragma unroll
        for (int nt = 0; nt < 8; nt++)
#pragma unroll
            for (int i = 0; i < 4; i++) sC[nt][i] = 0.f;
#pragma unroll
        for (int ks = 0; ks < 8; ks++) {
#pragma unroll
            for (int nt = 0; nt < 8; nt++) {
                int rb = nt * 8 + gid, cb = ks * 8 + tig;
                mma8(sC[nt], qua[ks], Ks[rb * QST + cb], Ks[rb * QST + cb + 4]);
            }
        }
        __syncthreads();   // all warps done reading Ks before exp(S) overwrite

        // Online softmax; write exp(S) (tf32) into Ks
#pragma unroll
        for (int hh = 0; hh < 2; hh++) {
            int qrow = w * 16 + gid + 8 * hh;
            float sv[16];
            float mx = -1e30f;
#pragma unroll
            for (int nt = 0; nt < 8; nt++) {
#pragma unroll
                for (int cc = 0; cc < 2; cc++) {
                    int jl = nt * 8 + 2 * tig + cc;
                    float s = sC[nt][2 * hh + cc] +
                              Es[qrow * EST + 63 + jl - qrow];
                    sv[nt * 2 + cc] = s;
                    mx = fmaxf(mx, s);
                }
            }
            mx = fmaxf(mx, __shfl_xor_sync(0xffffffffu, mx, 1));
            mx = fmaxf(mx, __shfl_xor_sync(0xffffffffu, mx, 2));
            float mn = fmaxf(m_i[hh], mx);
            float al = __expf(m_i[hh] - mn);
            float rs = 0.f;
#pragma unroll
            for (int t = 0; t < 16; t++) {
                float p = __expf(sv[t] - mn);
                rs += p;
                int nt = t >> 1, cc = t & 1;
                int jl = nt * 8 + 2 * tig + cc;
                Ks[qrow * QST + jl] = f2tf(p);
            }
            rs += __shfl_xor_sync(0xffffffffu, rs, 1);
            rs += __shfl_xor_sync(0xffffffffu, rs, 2);
            l_i[hh] = l_i[hh] * al + rs;
            m_i[hh] = mn;
#pragma unroll
            for (int nt = 0; nt < 8; nt++) {
                oC[nt][2 * hh] *= al;
                oC[nt][2 * hh + 1] *= al;
            }
        }
        __syncwarp();   // exp tile rows are warp-local: warp sync suffices

        // O += exp(S) @ V
#pragma unroll
        for (int ks = 0; ks < 8; ks++) {
            uint32_t a[4];
            int rb = w * 16 + gid, cb = ks * 8 + tig;
            a[0] = Ks[rb * QST + cb];
            a[1] = Ks[(rb + 8) * QST + cb];
            a[2] = Ks[rb * QST + cb + 4];
            a[3] = Ks[(rb + 8) * QST + cb + 4];
#pragma unroll
            for (int nt = 0; nt < 8; nt++) {
                uint32_t b0 = Vs[(ks * 8 + tig) * QST + nt * 8 + gid];
                uint32_t b1 = Vs[(ks * 8 + tig + 4) * QST + nt * 8 + gid];
                mma8(oC[nt], a, b0, b1);
            }
        }
    }

    // Write normalized output: att[b, t, h*64+d]
#pragma unroll
    for (int hh = 0; hh < 2; hh++) {
        int t = i0 + w * 16 + gid + 8 * hh;
        float inv = 1.f / l_i[hh];
#pragma unroll
        for (int nt = 0; nt < 8; nt++) {
            int d = nt * 8 + 2 * tig;
            size_t o = (((size_t)b * 1024 + t) * 8 + h) * 64 + d;
            att[o]     = oC[nt][2 * hh] * inv;
            att[o + 1] = oC[nt][2 * hh + 1] * inv;
        }
    }
}

// ---------------------------------------------------------------------------
extern "C" void kernel_launch(void* const* d_in, const int* in_sizes, int n_in,
                              void* d_out, int out_size)
{
    const float* query = (const float*)d_in[0];
    const float* key   = (const float*)d_in[1];
    const float* value = (const float*)d_in[2];
    const float* pos   = (const float*)d_in[3];
    const float* Wq    = (const float*)d_in[4];
    const float* bq    = (const float*)d_in[5];
    const float* Wk    = (const float*)d_in[6];
    const float* bk    = (const float*)d_in[7];
    const float* Wv    = (const float*)d_in[8];
    const float* bv_   = (const float*)d_in[9];
    const float* Wp    = (const float*)d_in[10];
    const float* Wo    = (const float*)d_in[11];
    const float* bo    = (const float*)d_in[12];
    const float* pbu   = (const float*)d_in[13];
    const float* pbv   = (const float*)d_in[14];

    float *qu_p, *qv_p, *k_p, *v_p, *p_p, *att_p;
    cudaGetSymbolAddress((void**)&qu_p,  g_qu);
    cudaGetSymbolAddress((void**)&qv_p,  g_qv);
    cudaGetSymbolAddress((void**)&k_p,   g_k);
    cudaGetSymbolAddress((void**)&v_p,   g_v);
    cudaGetSymbolAddress((void**)&p_p,   g_p);
    cudaGetSymbolAddress((void**)&att_p, g_att);

    cudaFuncSetAttribute(attn_mma,
                         cudaFuncAttributeMaxDynamicSharedMemorySize,
                         ATT_SMEM_BYTES);

    dim3 thr(256);
    const float scale = 0.125f;   // 1/sqrt(64)

    gemm_mma<<<dim3(4, 64), thr>>>(query, Wq, bq, pbu, pbv,
                                   qu_p, qv_p, 8192, 2, scale);
    gemm_mma<<<dim3(4, 64), thr>>>(key,   Wk, bk, nullptr, nullptr,
                                   k_p, nullptr, 8192, 1, 1.f);
    gemm_mma<<<dim3(4, 64), thr>>>(value, Wv, bv_, nullptr, nullptr,
                                   v_p, nullptr, 8192, 1, 1.f);
    gemm_mma<<<dim3(4, 16), thr>>>(pos,   Wp, nullptr, nullptr, nullptr,
                                   p_p, nullptr, 2047, 3, 1.f);

    attn_mma<<<dim3(16, 64), dim3(128), ATT_SMEM_BYTES>>>(qu_p, qv_p, k_p, v_p,
                                                          p_p, att_p);

    gemm_mma<<<dim3(4, 64), thr>>>(att_p, Wo, bo, nullptr, nullptr,
                                   (float*)d_out, nullptr, 8192, 0, 1.f);
}

// round 4
// speedup vs baseline: 2.1330x; 1.0413x over previous
#include <cuda_runtime.h>
#include <cstdint>

// Problem constants: B=8, T=1024, F=512, H=8, D=64, P=2047
__device__ float g_qu[8 * 8 * 1024 * 64];   // [B,H,T,D] (q + pos_bias_u) * scale
__device__ float g_qv[8 * 8 * 1024 * 64];   // [B,H,T,D] (q + pos_bias_v) * scale
__device__ float g_k [8 * 8 * 1024 * 64];   // [B,H,T,D]
__device__ float g_v [8 * 8 * 1024 * 64];   // [B,H,T,D]
__device__ float g_p [8 * 2047 * 64];       // [H,P,D]
__device__ float g_att[8 * 1024 * 512];     // [B*T, F]

__device__ __forceinline__ uint32_t f2tf(float x) {
    uint32_t r;
    asm("cvt.rna.tf32.f32 %0, %1;" : "=r"(r) : "f"(x));
    return r;
}

__device__ __forceinline__ void mma8(float c[4], const uint32_t a[4],
                                     uint32_t b0, uint32_t b1) {
    asm volatile(
        "mma.sync.aligned.m16n8k8.row.col.f32.tf32.tf32.f32 "
        "{%0,%1,%2,%3},{%4,%5,%6,%7},{%8,%9},{%0,%1,%2,%3};"
        : "+f"(c[0]), "+f"(c[1]), "+f"(c[2]), "+f"(c[3])
        : "r"(a[0]), "r"(a[1]), "r"(a[2]), "r"(a[3]), "r"(b0), "r"(b1));
}

// ---------------------------------------------------------------------------
// TF32 NT GEMM: C[m,n] = sum_k A[m,k]*W[n,k] (+bias). N=K=512.
// Block tile 128x64, BK=32, 256 threads = 8 warps (4m x 2n), warp tile 32x32.
// 512 blocks for M=8192 -> fills the chip (vs 256 before).
// mode 0: out1[m*512+n] = acc + bias[n]
// mode 1: out1[BHTD]    = acc + bias[n]
// mode 2: out1 = (acc+bias+bu)*scale, out2 = (acc+bias+bv)*scale  (BHTD)
// mode 3: out1[(h*2047+m)*64+d] = acc
// ---------------------------------------------------------------------------
#define AST 36
__global__ __launch_bounds__(256) void gemm_mma(
    const float* __restrict__ A, const float* __restrict__ W,
    const float* __restrict__ bias, const float* __restrict__ bu,
    const float* __restrict__ bv,
    float* __restrict__ out1, float* __restrict__ out2,
    int M, int mode, float scale)
{
    __shared__ uint32_t As[128 * AST];
    __shared__ uint32_t Ws[64 * AST];

    const int tid = threadIdx.x;
    const int warp = tid >> 5, lane = tid & 31;
    const int gid = lane >> 2, tig = lane & 3;
    const int wm = warp & 3, wn = warp >> 2;
    const int m0 = blockIdx.y * 128, n0 = blockIdx.x * 64;
    if (m0 >= M) return;

    float acc[2][4][4];
#pragma unroll
    for (int mt = 0; mt < 2; mt++)
#pragma unroll
        for (int nt = 0; nt < 4; nt++)
#pragma unroll
            for (int i = 0; i < 4; i++) acc[mt][nt][i] = 0.f;

    for (int k0 = 0; k0 < 512; k0 += 32) {
#pragma unroll
        for (int r = 0; r < 4; r++) {
            int idx = tid + r * 256;
            int row = idx >> 3, c4 = (idx & 7) << 2;
            float4 av = make_float4(0.f, 0.f, 0.f, 0.f);
            if (m0 + row < M)
                av = *(const float4*)(A + (size_t)(m0 + row) * 512 + k0 + c4);
            uint32_t* da = &As[row * AST + c4];
            da[0] = f2tf(av.x); da[1] = f2tf(av.y);
            da[2] = f2tf(av.z); da[3] = f2tf(av.w);
        }
#pragma unroll
        for (int r = 0; r < 2; r++) {
            int idx = tid + r * 256;
            int row = idx >> 3, c4 = (idx & 7) << 2;
            float4 wv = *(const float4*)(W + (size_t)(n0 + row) * 512 + k0 + c4);
            uint32_t* dw = &Ws[row * AST + c4];
            dw[0] = f2tf(wv.x); dw[1] = f2tf(wv.y);
            dw[2] = f2tf(wv.z); dw[3] = f2tf(wv.w);
        }
        __syncthreads();
#pragma unroll
        for (int ks = 0; ks < 4; ks++) {
            uint32_t a[2][4];
#pragma unroll
            for (int mt = 0; mt < 2; mt++) {
                int rb = wm * 32 + mt * 16 + gid;
                int cb = ks * 8 + tig;
                a[mt][0] = As[rb * AST + cb];
                a[mt][1] = As[(rb + 8) * AST + cb];
                a[mt][2] = As[rb * AST + cb + 4];
                a[mt][3] = As[(rb + 8) * AST + cb + 4];
            }
#pragma unroll
            for (int nt = 0; nt < 4; nt++) {
                int nb = wn * 32 + nt * 8 + gid;
                uint32_t b0 = Ws[nb * AST + ks * 8 + tig];
                uint32_t b1 = Ws[nb * AST + ks * 8 + tig + 4];
                mma8(acc[0][nt], a[0], b0, b1);
                mma8(acc[1][nt], a[1], b0, b1);
            }
        }
        __syncthreads();
    }

#pragma unroll
    for (int mt = 0; mt < 2; mt++) {
#pragma unroll
        for (int hh = 0; hh < 2; hh++) {
            int m = m0 + wm * 32 + mt * 16 + gid + 8 * hh;
            if (m >= M) continue;
#pragma unroll
            for (int nt = 0; nt < 4; nt++) {
#pragma unroll
                for (int cc = 0; cc < 2; cc++) {
                    int n = n0 + wn * 32 + nt * 8 + 2 * tig + cc;
                    float v = acc[mt][nt][2 * hh + cc];
                    if (mode == 0) {
                        out1[(size_t)m * 512 + n] = v + bias[n];
                    } else if (mode == 1) {
                        int b = m >> 10, t = m & 1023, h = n >> 6, d = n & 63;
                        out1[(((size_t)(b * 8 + h) << 10) + t) * 64 + d] =
                            v + bias[n];
                    } else if (mode == 2) {
                        int b = m >> 10, t = m & 1023, h = n >> 6, d = n & 63;
                        size_t idx = (((size_t)(b * 8 + h) << 10) + t) * 64 + d;
                        float base = v + bias[n];
                        out1[idx] = (base + bu[n]) * scale;
                        out2[idx] = (base + bv[n]) * scale;
                    } else {
                        int h = n >> 6, d = n & 63;
                        out1[((size_t)h * 2047 + m) * 64 + d] = v;
                    }
                }
            }
        }
    }
}

// ---------------------------------------------------------------------------
// Tensor-core flash attention with relative positions.
// scores[i,j] = qu[i]·k[j] + comp[i][j], comp[i][j] = (Qv·P_slab^T)[i][63+j-i]
// written compacted+predicated straight from the E-GEMM fragments (warp-local).
// Block = 64 queries of one (b,h); 128 threads = 4 warps; warp owns 16 rows.
// smem 87KB (Q staging overlaid on K/V) -> 2 CTAs/SM.
// ---------------------------------------------------------------------------
#define QST 68
#define ATT_SMEM_U32 (2 * 64 * QST + 128 * QST + 64 * QST)
#define ATT_SMEM_BYTES (ATT_SMEM_U32 * 4)

__global__ __launch_bounds__(128) void attn_mma(
    const float* __restrict__ qu, const float* __restrict__ qv,
    const float* __restrict__ kk, const float* __restrict__ vv,
    const float* __restrict__ pp, float* __restrict__ att)
{
    extern __shared__ uint32_t sh[];
    uint32_t* Ks = sh;                       // Qu staging, then K / exp(S)
    uint32_t* Vs = sh + 64 * QST;            // Qv staging, then V
    uint32_t* Ps = sh + 2 * 64 * QST;        // 128-row P slab
    float*    Cp = (float*)(sh + 2 * 64 * QST + 128 * QST);  // 64x68 compacted E

    const int tid = threadIdx.x;
    const int w = tid >> 5, lane = tid & 31;
    const int gid = lane >> 2, tig = lane & 3;
    const int i0 = blockIdx.x << 6;
    const int bh = blockIdx.y;
    const int h = bh & 7, b = bh >> 3;

    // Stage Q tiles (tf32) into the K/V buffers, extract fragments, release.
#pragma unroll
    for (int r = 0; r < 8; r++) {
        int fi = tid + r * 128;
        int row = fi >> 4, c4 = (fi & 15) << 2;
        size_t g = ((size_t)bh * 1024 + i0 + row) * 64 + c4;
        float4 u = *(const float4*)(qu + g);
        float4 v = *(const float4*)(qv + g);
        uint32_t* du = &Ks[row * QST + c4];
        du[0] = f2tf(u.x); du[1] = f2tf(u.y); du[2] = f2tf(u.z); du[3] = f2tf(u.w);
        uint32_t* dv = &Vs[row * QST + c4];
        dv[0] = f2tf(v.x); dv[1] = f2tf(v.y); dv[2] = f2tf(v.z); dv[3] = f2tf(v.w);
    }
    __syncthreads();

    uint32_t qua[8][4], qva[8][4];
#pragma unroll
    for (int ks = 0; ks < 8; ks++) {
        int rb = w * 16 + gid, cb = ks * 8 + tig;
        qua[ks][0] = Ks[rb * QST + cb];
        qua[ks][1] = Ks[(rb + 8) * QST + cb];
        qua[ks][2] = Ks[rb * QST + cb + 4];
        qua[ks][3] = Ks[(rb + 8) * QST + cb + 4];
        qva[ks][0] = Vs[rb * QST + cb];
        qva[ks][1] = Vs[(rb + 8) * QST + cb];
        qva[ks][2] = Vs[rb * QST + cb + 4];
        qva[ks][3] = Vs[(rb + 8) * QST + cb + 4];
    }

    float m_i[2] = {-1e30f, -1e30f}, l_i[2] = {0.f, 0.f};
    float oC[8][4];
#pragma unroll
    for (int nt = 0; nt < 8; nt++)
#pragma unroll
        for (int i = 0; i < 4; i++) oC[nt][i] = 0.f;

    for (int jt = 0; jt < 16; jt++) {
        const int j0 = jt << 6;
        __syncthreads();   // prior iteration (and Q staging) done with smem

        // Load K, V tiles
#pragma unroll
        for (int r = 0; r < 8; r++) {
            int fi = tid + r * 128;
            int row = fi >> 4, c4 = (fi & 15) << 2;
            size_t g = ((size_t)bh * 1024 + j0 + row) * 64 + c4;
            float4 kv = *(const float4*)(kk + g);
            float4 vf = *(const float4*)(vv + g);
            uint32_t* dk = &Ks[row * QST + c4];
            dk[0] = f2tf(kv.x); dk[1] = f2tf(kv.y);
            dk[2] = f2tf(kv.z); dk[3] = f2tf(kv.w);
            uint32_t* dv = &Vs[row * QST + c4];
            dv[0] = f2tf(vf.x); dv[1] = f2tf(vf.y);
            dv[2] = f2tf(vf.z); dv[3] = f2tf(vf.w);
        }
        // Load P slab rows rbase..rbase+127 (row 127 pads an unused E col)
        const int rbase = 960 + j0 - i0;
#pragma unroll
        for (int r = 0; r < 16; r++) {
            int fi = tid + r * 128;
            int row = fi >> 4, c4 = (fi & 15) << 2;
            int prow = rbase + row;
            prow = prow > 2046 ? 2046 : prow;
            float4 pv = *(const float4*)(pp + ((size_t)h * 2047 + prow) * 64 + c4);
            uint32_t* dp = &Ps[row * QST + c4];
            dp[0] = f2tf(pv.x); dp[1] = f2tf(pv.y);
            dp[2] = f2tf(pv.z); dp[3] = f2tf(pv.w);
        }
        __syncthreads();

        // E = Qv @ P_slab^T, written compacted: Cp[i][j] = E[i][63+j-i].
        // Rows of E handled by warp w are exactly its softmax rows.
#pragma unroll
        for (int nt = 0; nt < 16; nt++) {
            float e[4] = {0.f, 0.f, 0.f, 0.f};
#pragma unroll
            for (int ks = 0; ks < 8; ks++) {
                int rb = nt * 8 + gid, cb = ks * 8 + tig;
                mma8(e, qva[ks], Ps[rb * QST + cb], Ps[rb * QST + cb + 4]);
            }
            int er = w * 16 + gid, ec = nt * 8 + 2 * tig;
#pragma unroll
            for (int hh = 0; hh < 2; hh++) {
#pragma unroll
                for (int cc = 0; cc < 2; cc++) {
                    int row = er + 8 * hh;
                    int col = ec + cc - 63 + row;   // j index
                    if (col >= 0 && col < 64)
                        Cp[row * QST + col] = e[2 * hh + cc];
                }
            }
        }

        // S1 = Qu @ K^T
        float sC[8][4];
#pragma unroll
        for (int nt = 0; nt < 8; nt++)
#pragma unroll
            for (int i = 0; i < 4; i++) sC[nt][i] = 0.f;
#pragma unroll
        for (int ks = 0; ks < 8; ks++) {
#pragma unroll
            for (int nt = 0; nt < 8; nt++) {
                int rb = nt * 8 + gid, cb = ks * 8 + tig;
                mma8(sC[nt], qua[ks], Ks[rb * QST + cb], Ks[rb * QST + cb + 4]);
            }
        }
        __syncthreads();   // all warps done reading Ks before exp overwrite

        // Online softmax; write exp(S) (tf32) into own warp's Ks rows
#pragma unroll
        for (int hh = 0; hh < 2; hh++) {
            int qrow = w * 16 + gid + 8 * hh;
            float sv[16];
            float mx = -1e30f;
#pragma unroll
            for (int nt = 0; nt < 8; nt++) {
#pragma unroll
                for (int cc = 0; cc < 2; cc++) {
                    int jl = nt * 8 + 2 * tig + cc;
                    float s = sC[nt][2 * hh + cc] + Cp[qrow * QST + jl];
                    sv[nt * 2 + cc] = s;
                    mx = fmaxf(mx, s);
                }
            }
            mx = fmaxf(mx, __shfl_xor_sync(0xffffffffu, mx, 1));
            mx = fmaxf(mx, __shfl_xor_sync(0xffffffffu, mx, 2));
            float mn = fmaxf(m_i[hh], mx);
            float al = __expf(m_i[hh] - mn);
            float rs = 0.f;
#pragma unroll
            for (int t = 0; t < 16; t++) {
                float p = __expf(sv[t] - mn);
                rs += p;
                int nt = t >> 1, cc = t & 1;
                int jl = nt * 8 + 2 * tig + cc;
                Ks[qrow * QST + jl] = f2tf(p);
            }
            rs += __shfl_xor_sync(0xffffffffu, rs, 1);
            rs += __shfl_xor_sync(0xffffffffu, rs, 2);
            l_i[hh] = l_i[hh] * al + rs;
            m_i[hh] = mn;
#pragma unroll
            for (int nt = 0; nt < 8; nt++) {
                oC[nt][2 * hh] *= al;
                oC[nt][2 * hh + 1] *= al;
            }
        }
        __syncwarp();   // exp tile rows are warp-local

        // O += exp(S) @ V
#pragma unroll
        for (int ks = 0; ks < 8; ks++) {
            uint32_t a[4];
            int rb = w * 16 + gid, cb = ks * 8 + tig;
            a[0] = Ks[rb * QST + cb];
            a[1] = Ks[(rb + 8) * QST + cb];
            a[2] = Ks[rb * QST + cb + 4];
            a[3] = Ks[(rb + 8) * QST + cb + 4];
#pragma unroll
            for (int nt = 0; nt < 8; nt++) {
                uint32_t b0 = Vs[(ks * 8 + tig) * QST + nt * 8 + gid];
                uint32_t b1 = Vs[(ks * 8 + tig + 4) * QST + nt * 8 + gid];
                mma8(oC[nt], a, b0, b1);
            }
        }
    }

    // Write normalized output: att[b, t, h*64+d]
#pragma unroll
    for (int hh = 0; hh < 2; hh++) {
        int t = i0 + w * 16 + gid + 8 * hh;
        float inv = 1.f / l_i[hh];
#pragma unroll
        for (int nt = 0; nt < 8; nt++) {
            int d = nt * 8 + 2 * tig;
            size_t o = (((size_t)b * 1024 + t) * 8 + h) * 64 + d;
            att[o]     = oC[nt][2 * hh] * inv;
            att[o + 1] = oC[nt][2 * hh + 1] * inv;
        }
    }
}

// ---------------------------------------------------------------------------
extern "C" void kernel_launch(void* const* d_in, const int* in_sizes, int n_in,
                              void* d_out, int out_size)
{
    const float* query = (const float*)d_in[0];
    const float* key   = (const float*)d_in[1];
    const float* value = (const float*)d_in[2];
    const float* pos   = (const float*)d_in[3];
    const float* Wq    = (const float*)d_in[4];
    const float* bq    = (const float*)d_in[5];
    const float* Wk    = (const float*)d_in[6];
    const float* bk    = (const float*)d_in[7];
    const float* Wv    = (const float*)d_in[8];
    const float* bv_   = (const float*)d_in[9];
    const float* Wp    = (const float*)d_in[10];
    const float* Wo    = (const float*)d_in[11];
    const float* bo    = (const float*)d_in[12];
    const float* pbu   = (const float*)d_in[13];
    const float* pbv   = (const float*)d_in[14];

    float *qu_p, *qv_p, *k_p, *v_p, *p_p, *att_p;
    cudaGetSymbolAddress((void**)&qu_p,  g_qu);
    cudaGetSymbolAddress((void**)&qv_p,  g_qv);
    cudaGetSymbolAddress((void**)&k_p,   g_k);
    cudaGetSymbolAddress((void**)&v_p,   g_v);
    cudaGetSymbolAddress((void**)&p_p,   g_p);
    cudaGetSymbolAddress((void**)&att_p, g_att);

    cudaFuncSetAttribute(attn_mma,
                         cudaFuncAttributeMaxDynamicSharedMemorySize,
                         ATT_SMEM_BYTES);

    dim3 thr(256);
    const float scale = 0.125f;   // 1/sqrt(64)

    gemm_mma<<<dim3(8, 64), thr>>>(query, Wq, bq, pbu, pbv,
                                   qu_p, qv_p, 8192, 2, scale);
    gemm_mma<<<dim3(8, 64), thr>>>(key,   Wk, bk, nullptr, nullptr,
                                   k_p, nullptr, 8192, 1, 1.f);
    gemm_mma<<<dim3(8, 64), thr>>>(value, Wv, bv_, nullptr, nullptr,
                                   v_p, nullptr, 8192, 1, 1.f);
    gemm_mma<<<dim3(8, 16), thr>>>(pos,   Wp, nullptr, nullptr, nullptr,
                                   p_p, nullptr, 2047, 3, 1.f);

    attn_mma<<<dim3(16, 64), dim3(128), ATT_SMEM_BYTES>>>(qu_p, qv_p, k_p, v_p,
                                                          p_p, att_p);

    gemm_mma<<<dim3(8, 64), thr>>>(att_p, Wo, bo, nullptr, nullptr,
                                   (float*)d_out, nullptr, 8192, 0, 1.f);
}

// round 7
// speedup vs baseline: 3.2067x; 1.5033x over previous
#include <cuda_runtime.h>
#include <cstdint>

// Problem constants: B=8, T=1024, F=512, H=8, D=64, P=2047
__device__ float g_qu[8 * 8 * 1024 * 64];   // [B,H,T,D] (q + pos_bias_u) * scale
__device__ float g_qv[8 * 8 * 1024 * 64];   // [B,H,T,D] (q + pos_bias_v) * scale
__device__ float g_k [8 * 8 * 1024 * 64];   // [B,H,T,D]
__device__ float g_v [8 * 8 * 1024 * 64];   // [B,H,T,D]
__device__ float g_p [8 * 2047 * 64];       // [H,P,D]
__device__ float g_att[8 * 1024 * 512];     // [B*T, F]

__device__ __forceinline__ uint32_t f2tf(float x) {
    uint32_t r;
    asm("cvt.rna.tf32.f32 %0, %1;" : "=r"(r) : "f"(x));
    return r;
}

__device__ __forceinline__ void mma8(float c[4], const uint32_t a[4],
                                     uint32_t b0, uint32_t b1) {
    asm volatile(
        "mma.sync.aligned.m16n8k8.row.col.f32.tf32.tf32.f32 "
        "{%0,%1,%2,%3},{%4,%5,%6,%7},{%8,%9},{%0,%1,%2,%3};"
        : "+f"(c[0]), "+f"(c[1]), "+f"(c[2]), "+f"(c[3])
        : "r"(a[0]), "r"(a[1]), "r"(a[2]), "r"(a[3]), "r"(b0), "r"(b1));
}

// ---------------------------------------------------------------------------
// TF32 NT GEMM core: C[m,n] = sum_k A[m,k]*W[n,k]. N=K=512.
// Block tile 128x64, BK=32, register-prefetch double buffering (no cp.async).
// 256 threads = 8 warps (4m x 2n), warp tile 32x32.
// ---------------------------------------------------------------------------
#define AST 36

__device__ __forceinline__ void gemm_core(
    const float* __restrict__ A, const float* __restrict__ W, int M,
    int m0, int n0, uint32_t* As, uint32_t* Ws, float acc[2][4][4])
{
    const int tid = threadIdx.x;
    const int warp = tid >> 5, lane = tid & 31;
    const int gid = lane >> 2, tig = lane & 3;
    const int wm = warp & 3, wn = warp >> 2;

#pragma unroll
    for (int mt = 0; mt < 2; mt++)
#pragma unroll
        for (int nt = 0; nt < 4; nt++)
#pragma unroll
            for (int i = 0; i < 4; i++) acc[mt][nt][i] = 0.f;

    // Per-thread staging coordinates
    //   A: 4 chunks of (row, c4);  W: 2 chunks
    float4 pa[4], pw[2];

    // Prefetch k0 = 0
#pragma unroll
    for (int r = 0; r < 4; r++) {
        int ch = tid + r * 256;
        int row = ch >> 3, c4 = (ch & 7) << 2;
        int gm = m0 + row;
        pa[r] = (gm < M) ? *(const float4*)(A + (size_t)gm * 512 + c4)
                         : make_float4(0.f, 0.f, 0.f, 0.f);
    }
#pragma unroll
    for (int r = 0; r < 2; r++) {
        int ch = tid + r * 256;
        int row = ch >> 3, c4 = (ch & 7) << 2;
        pw[r] = *(const float4*)(W + (size_t)(n0 + row) * 512 + c4);
    }

    for (int it = 0; it < 16; it++) {
        // Commit prefetched tile to smem (tf32)
#pragma unroll
        for (int r = 0; r < 4; r++) {
            int ch = tid + r * 256;
            int row = ch >> 3, c4 = (ch & 7) << 2;
            uint32_t* da = &As[row * AST + c4];
            da[0] = f2tf(pa[r].x); da[1] = f2tf(pa[r].y);
            da[2] = f2tf(pa[r].z); da[3] = f2tf(pa[r].w);
        }
#pragma unroll
        for (int r = 0; r < 2; r++) {
            int ch = tid + r * 256;
            int row = ch >> 3, c4 = (ch & 7) << 2;
            uint32_t* dw = &Ws[row * AST + c4];
            dw[0] = f2tf(pw[r].x); dw[1] = f2tf(pw[r].y);
            dw[2] = f2tf(pw[r].z); dw[3] = f2tf(pw[r].w);
        }
        __syncthreads();

        // Prefetch next tile into registers (latency overlapped with mma)
        if (it + 1 < 16) {
            int k0 = (it + 1) * 32;
#pragma unroll
            for (int r = 0; r < 4; r++) {
                int ch = tid + r * 256;
                int row = ch >> 3, c4 = (ch & 7) << 2;
                int gm = m0 + row;
                pa[r] = (gm < M)
                    ? *(const float4*)(A + (size_t)gm * 512 + k0 + c4)
                    : make_float4(0.f, 0.f, 0.f, 0.f);
            }
#pragma unroll
            for (int r = 0; r < 2; r++) {
                int ch = tid + r * 256;
                int row = ch >> 3, c4 = (ch & 7) << 2;
                pw[r] = *(const float4*)(W + (size_t)(n0 + row) * 512 + k0 + c4);
            }
        }

        // Compute current tile from smem
#pragma unroll
        for (int ks = 0; ks < 4; ks++) {
            uint32_t a[2][4];
#pragma unroll
            for (int mt = 0; mt < 2; mt++) {
                int rb = wm * 32 + mt * 16 + gid, cb = ks * 8 + tig;
                a[mt][0] = As[rb * AST + cb];
                a[mt][1] = As[(rb + 8) * AST + cb];
                a[mt][2] = As[rb * AST + cb + 4];
                a[mt][3] = As[(rb + 8) * AST + cb + 4];
            }
#pragma unroll
            for (int nt = 0; nt < 4; nt++) {
                int nb = wn * 32 + nt * 8 + gid;
                uint32_t b0 = Ws[nb * AST + ks * 8 + tig];
                uint32_t b1 = Ws[nb * AST + ks * 8 + tig + 4];
                mma8(acc[0][nt], a[0], b0, b1);
                mma8(acc[1][nt], a[1], b0, b1);
            }
        }
        __syncthreads();
    }
}

// Fused Q/K/V/P projection GEMM. blockIdx.z selects operand set.
__global__ __launch_bounds__(256) void gemm_fused(
    const float* __restrict__ query, const float* __restrict__ key,
    const float* __restrict__ value, const float* __restrict__ pos,
    const float* __restrict__ Wq, const float* __restrict__ Wk,
    const float* __restrict__ Wv, const float* __restrict__ Wp,
    const float* __restrict__ bq, const float* __restrict__ bk,
    const float* __restrict__ bvb, const float* __restrict__ bu,
    const float* __restrict__ bvv,
    float* __restrict__ o_qu, float* __restrict__ o_qv,
    float* __restrict__ o_k, float* __restrict__ o_v,
    float* __restrict__ o_p)
{
    __shared__ uint32_t As[128 * AST];
    __shared__ uint32_t Ws[64 * AST];

    const int z = blockIdx.z;
    const float *A, *W;
    int M;
    if (z == 0)      { A = query; W = Wq; M = 8192; }
    else if (z == 1) { A = key;   W = Wk; M = 8192; }
    else if (z == 2) { A = value; W = Wv; M = 8192; }
    else             { A = pos;   W = Wp; M = 2047; }

    const int m0 = blockIdx.y * 128, n0 = blockIdx.x * 64;
    if (m0 >= M) return;

    float acc[2][4][4];
    gemm_core(A, W, M, m0, n0, As, Ws, acc);

    const int tid = threadIdx.x;
    const int warp = tid >> 5, lane = tid & 31;
    const int gid = lane >> 2, tig = lane & 3;
    const int wm = warp & 3, wn = warp >> 2;
    const float scale = 0.125f;

#pragma unroll
    for (int mt = 0; mt < 2; mt++) {
#pragma unroll
        for (int hh = 0; hh < 2; hh++) {
            int m = m0 + wm * 32 + mt * 16 + gid + 8 * hh;
            if (m >= M) continue;
#pragma unroll
            for (int nt = 0; nt < 4; nt++) {
#pragma unroll
                for (int cc = 0; cc < 2; cc++) {
                    int n = n0 + wn * 32 + nt * 8 + 2 * tig + cc;
                    float v = acc[mt][nt][2 * hh + cc];
                    if (z == 0) {
                        int b = m >> 10, t = m & 1023, h = n >> 6, d = n & 63;
                        size_t idx = (((size_t)(b * 8 + h) << 10) + t) * 64 + d;
                        float base = v + bq[n];
                        o_qu[idx] = (base + bu[n]) * scale;
                        o_qv[idx] = (base + bvv[n]) * scale;
                    } else if (z == 1) {
                        int b = m >> 10, t = m & 1023, h = n >> 6, d = n & 63;
                        o_k[(((size_t)(b * 8 + h) << 10) + t) * 64 + d] =
                            v + bk[n];
                    } else if (z == 2) {
                        int b = m >> 10, t = m & 1023, h = n >> 6, d = n & 63;
                        o_v[(((size_t)(b * 8 + h) << 10) + t) * 64 + d] =
                            v + bvb[n];
                    } else {
                        int h = n >> 6, d = n & 63;
                        o_p[((size_t)h * 2047 + m) * 64 + d] = v;
                    }
                }
            }
        }
    }
}

// Output projection GEMM: d_out = att @ Wo^T + bo.
__global__ __launch_bounds__(256) void gemm_out(
    const float* __restrict__ A, const float* __restrict__ W,
    const float* __restrict__ bias, float* __restrict__ out)
{
    __shared__ uint32_t As[128 * AST];
    __shared__ uint32_t Ws[64 * AST];

    const int m0 = blockIdx.y * 128, n0 = blockIdx.x * 64;
    float acc[2][4][4];
    gemm_core(A, W, 8192, m0, n0, As, Ws, acc);

    const int tid = threadIdx.x;
    const int warp = tid >> 5, lane = tid & 31;
    const int gid = lane >> 2, tig = lane & 3;
    const int wm = warp & 3, wn = warp >> 2;

#pragma unroll
    for (int mt = 0; mt < 2; mt++)
#pragma unroll
        for (int hh = 0; hh < 2; hh++) {
            int m = m0 + wm * 32 + mt * 16 + gid + 8 * hh;
#pragma unroll
            for (int nt = 0; nt < 4; nt++)
#pragma unroll
                for (int cc = 0; cc < 2; cc++) {
                    int n = n0 + wn * 32 + nt * 8 + 2 * tig + cc;
                    out[(size_t)m * 512 + n] = acc[mt][nt][2 * hh + cc] + bias[n];
                }
        }
}

// ---------------------------------------------------------------------------
// Tensor-core flash attention with relative positions (R4-proven skeleton +
// band-skipped E-GEMM).
// scores[i,j] = qu[i]·k[j] + comp[i][j], comp[i][j] = (Qv·P_slab^T)[i][63+j-i]
// Block = 64 queries of one (b,h); 128 threads = 4 warps; smem 87KB.
// ---------------------------------------------------------------------------
#define QST 68
#define ATT_SMEM_U32 (2 * 64 * QST + 128 * QST + 64 * QST)
#define ATT_SMEM_BYTES (ATT_SMEM_U32 * 4)

__global__ __launch_bounds__(128) void attn_mma(
    const float* __restrict__ qu, const float* __restrict__ qv,
    const float* __restrict__ kk, const float* __restrict__ vv,
    const float* __restrict__ pp, float* __restrict__ att)
{
    extern __shared__ uint32_t sh[];
    uint32_t* Ks = sh;                       // Qu staging, then K / exp(S)
    uint32_t* Vs = sh + 64 * QST;            // Qv staging, then V
    uint32_t* Ps = sh + 2 * 64 * QST;        // 128-row P slab
    float*    Cp = (float*)(sh + 2 * 64 * QST + 128 * QST);  // 64x68 band

    const int tid = threadIdx.x;
    const int w = tid >> 5, lane = tid & 31;
    const int gid = lane >> 2, tig = lane & 3;
    const int i0 = blockIdx.x << 6;
    const int bh = blockIdx.y;
    const int h = bh & 7, b = bh >> 3;

    // Stage Q tiles (tf32) into the K/V buffers, extract fragments, release.
#pragma unroll
    for (int r = 0; r < 8; r++) {
        int fi = tid + r * 128;
        int row = fi >> 4, c4 = (fi & 15) << 2;
        size_t g = ((size_t)bh * 1024 + i0 + row) * 64 + c4;
        float4 u = *(const float4*)(qu + g);
        float4 v = *(const float4*)(qv + g);
        uint32_t* du = &Ks[row * QST + c4];
        du[0] = f2tf(u.x); du[1] = f2tf(u.y); du[2] = f2tf(u.z); du[3] = f2tf(u.w);
        uint32_t* dv = &Vs[row * QST + c4];
        dv[0] = f2tf(v.x); dv[1] = f2tf(v.y); dv[2] = f2tf(v.z); dv[3] = f2tf(v.w);
    }
    __syncthreads();

    uint32_t qua[8][4], qva[8][4];
#pragma unroll
    for (int ks = 0; ks < 8; ks++) {
        int rb = w * 16 + gid, cb = ks * 8 + tig;
        qua[ks][0] = Ks[rb * QST + cb];
        qua[ks][1] = Ks[(rb + 8) * QST + cb];
        qua[ks][2] = Ks[rb * QST + cb + 4];
        qua[ks][3] = Ks[(rb + 8) * QST + cb + 4];
        qva[ks][0] = Vs[rb * QST + cb];
        qva[ks][1] = Vs[(rb + 8) * QST + cb];
        qva[ks][2] = Vs[rb * QST + cb + 4];
        qva[ks][3] = Vs[(rb + 8) * QST + cb + 4];
    }

    float m_i[2] = {-1e30f, -1e30f}, l_i[2] = {0.f, 0.f};
    float oC[8][4];
#pragma unroll
    for (int nt = 0; nt < 8; nt++)
#pragma unroll
        for (int i = 0; i < 4; i++) oC[nt][i] = 0.f;

    // E band window for this warp's 16 rows: cols [48-16w, 126-16w]
    const int lo = 48 - w * 16, hi = 126 - w * 16;

    for (int jt = 0; jt < 16; jt++) {
        const int j0 = jt << 6;
        __syncthreads();   // prior iteration (and Q staging) done with smem

        // Load K, V tiles
#pragma unroll
        for (int r = 0; r < 8; r++) {
            int fi = tid + r * 128;
            int row = fi >> 4, c4 = (fi & 15) << 2;
            size_t g = ((size_t)bh * 1024 + j0 + row) * 64 + c4;
            float4 kv = *(const float4*)(kk + g);
            float4 vf = *(const float4*)(vv + g);
            uint32_t* dk = &Ks[row * QST + c4];
            dk[0] = f2tf(kv.x); dk[1] = f2tf(kv.y);
            dk[2] = f2tf(kv.z); dk[3] = f2tf(kv.w);
            uint32_t* dv = &Vs[row * QST + c4];
            dv[0] = f2tf(vf.x); dv[1] = f2tf(vf.y);
            dv[2] = f2tf(vf.z); dv[3] = f2tf(vf.w);
        }
        // Load P slab rows rbase..rbase+127 (row 127 pads an unused E col)
        const int rbase = 960 + j0 - i0;
#pragma unroll
        for (int r = 0; r < 16; r++) {
            int fi = tid + r * 128;
            int row = fi >> 4, c4 = (fi & 15) << 2;
            int prow = rbase + row;
            prow = prow > 2046 ? 2046 : prow;
            float4 pv = *(const float4*)(pp + ((size_t)h * 2047 + prow) * 64 + c4);
            uint32_t* dp = &Ps[row * QST + c4];
            dp[0] = f2tf(pv.x); dp[1] = f2tf(pv.y);
            dp[2] = f2tf(pv.z); dp[3] = f2tf(pv.w);
        }
        __syncthreads();

        // E = Qv @ P_slab^T over band n-tiles only; write compacted.
#pragma unroll
        for (int nt = 0; nt < 16; nt++) {
            if (nt * 8 + 7 < lo || nt * 8 > hi) continue;
            float e[4] = {0.f, 0.f, 0.f, 0.f};
#pragma unroll
            for (int ks = 0; ks < 8; ks++) {
                int rb = nt * 8 + gid, cb = ks * 8 + tig;
                mma8(e, qva[ks], Ps[rb * QST + cb], Ps[rb * QST + cb + 4]);
            }
            int er = w * 16 + gid, ec = nt * 8 + 2 * tig;
#pragma unroll
            for (int hh = 0; hh < 2; hh++) {
#pragma unroll
                for (int cc = 0; cc < 2; cc++) {
                    int row = er + 8 * hh;
                    int col = ec + cc - 63 + row;   // j index
                    if (col >= 0 && col < 64)
                        Cp[row * QST + col] = e[2 * hh + cc];
                }
            }
        }

        // S1 = Qu @ K^T
        float sC[8][4];
#pragma unroll
        for (int nt = 0; nt < 8; nt++)
#pragma unroll
            for (int i = 0; i < 4; i++) sC[nt][i] = 0.f;
#pragma unroll
        for (int ks = 0; ks < 8; ks++) {
#pragma unroll
            for (int nt = 0; nt < 8; nt++) {
                int rb = nt * 8 + gid, cb = ks * 8 + tig;
                mma8(sC[nt], qua[ks], Ks[rb * QST + cb], Ks[rb * QST + cb + 4]);
            }
        }
        __syncthreads();   // all warps done reading Ks before exp overwrite

        // Online softmax; write exp(S) (tf32) into own warp's Ks rows
#pragma unroll
        for (int hh = 0; hh < 2; hh++) {
            int qrow = w * 16 + gid + 8 * hh;
            float sv[16];
            float mx = -1e30f;
#pragma unroll
            for (int nt = 0; nt < 8; nt++) {
#pragma unroll
                for (int cc = 0; cc < 2; cc++) {
                    int jl = nt * 8 + 2 * tig + cc;
                    float s = sC[nt][2 * hh + cc] + Cp[qrow * QST + jl];
                    sv[nt * 2 + cc] = s;
                    mx = fmaxf(mx, s);
                }
            }
            mx = fmaxf(mx, __shfl_xor_sync(0xffffffffu, mx, 1));
            mx = fmaxf(mx, __shfl_xor_sync(0xffffffffu, mx, 2));
            float mn = fmaxf(m_i[hh], mx);
            float al = __expf(m_i[hh] - mn);
            float rs = 0.f;
#pragma unroll
            for (int t = 0; t < 16; t++) {
                float p = __expf(sv[t] - mn);
                rs += p;
                int nt = t >> 1, cc = t & 1;
                int jl = nt * 8 + 2 * tig + cc;
                Ks[qrow * QST + jl] = f2tf(p);
            }
            rs += __shfl_xor_sync(0xffffffffu, rs, 1);
            rs += __shfl_xor_sync(0xffffffffu, rs, 2);
            l_i[hh] = l_i[hh] * al + rs;
            m_i[hh] = mn;
#pragma unroll
            for (int nt = 0; nt < 8; nt++) {
                oC[nt][2 * hh] *= al;
                oC[nt][2 * hh + 1] *= al;
            }
        }
        __syncwarp();   // exp tile rows are warp-local

        // O += exp(S) @ V
#pragma unroll
        for (int ks = 0; ks < 8; ks++) {
            uint32_t a[4];
            int rb = w * 16 + gid, cb = ks * 8 + tig;
            a[0] = Ks[rb * QST + cb];
            a[1] = Ks[(rb + 8) * QST + cb];
            a[2] = Ks[rb * QST + cb + 4];
            a[3] = Ks[(rb + 8) * QST + cb + 4];
#pragma unroll
            for (int nt = 0; nt < 8; nt++) {
                uint32_t b0 = Vs[(ks * 8 + tig) * QST + nt * 8 + gid];
                uint32_t b1 = Vs[(ks * 8 + tig + 4) * QST + nt * 8 + gid];
                mma8(oC[nt], a, b0, b1);
            }
        }
    }

    // Write normalized output: att[b, t, h*64+d]
#pragma unroll
    for (int hh = 0; hh < 2; hh++) {
        int t = i0 + w * 16 + gid + 8 * hh;
        float inv = 1.f / l_i[hh];
#pragma unroll
        for (int nt = 0; nt < 8; nt++) {
            int d = nt * 8 + 2 * tig;
            size_t o = (((size_t)b * 1024 + t) * 8 + h) * 64 + d;
            att[o]     = oC[nt][2 * hh] * inv;
            att[o + 1] = oC[nt][2 * hh + 1] * inv;
        }
    }
}

// ---------------------------------------------------------------------------
extern "C" void kernel_launch(void* const* d_in, const int* in_sizes, int n_in,
                              void* d_out, int out_size)
{
    const float* query = (const float*)d_in[0];
    const float* key   = (const float*)d_in[1];
    const float* value = (const float*)d_in[2];
    const float* pos   = (const float*)d_in[3];
    const float* Wq    = (const float*)d_in[4];
    const float* bq    = (const float*)d_in[5];
    const float* Wk    = (const float*)d_in[6];
    const float* bk    = (const float*)d_in[7];
    const float* Wv    = (const float*)d_in[8];
    const float* bv_   = (const float*)d_in[9];
    const float* Wp    = (const float*)d_in[10];
    const float* Wo    = (const float*)d_in[11];
    const float* bo    = (const float*)d_in[12];
    const float* pbu   = (const float*)d_in[13];
    const float* pbv   = (const float*)d_in[14];

    float *qu_p, *qv_p, *k_p, *v_p, *p_p, *att_p;
    cudaGetSymbolAddress((void**)&qu_p,  g_qu);
    cudaGetSymbolAddress((void**)&qv_p,  g_qv);
    cudaGetSymbolAddress((void**)&k_p,   g_k);
    cudaGetSymbolAddress((void**)&v_p,   g_v);
    cudaGetSymbolAddress((void**)&p_p,   g_p);
    cudaGetSymbolAddress((void**)&att_p, g_att);

    cudaFuncSetAttribute(attn_mma,
                         cudaFuncAttributeMaxDynamicSharedMemorySize,
                         ATT_SMEM_BYTES);

    gemm_fused<<<dim3(8, 64, 4), 256>>>(
        query, key, value, pos, Wq, Wk, Wv, Wp,
        bq, bk, bv_, pbu, pbv,
        qu_p, qv_p, k_p, v_p, p_p);

    attn_mma<<<dim3(16, 64), dim3(128), ATT_SMEM_BYTES>>>(qu_p, qv_p, k_p, v_p,
                                                          p_p, att_p);

    gemm_out<<<dim3(8, 64), 256>>>(att_p, Wo, bo, (float*)d_out);
}

// round 8
// speedup vs baseline: 3.6889x; 1.1504x over previous
#include <cuda_runtime.h>
#include <cstdint>

// Problem constants: B=8, T=1024, F=512, H=8, D=64, P=2047
__device__ float g_qu[8 * 8 * 1024 * 64];   // [B,H,T,D] (q + pos_bias_u) * scale
__device__ float g_qv[8 * 8 * 1024 * 64];   // [B,H,T,D] (q + pos_bias_v) * scale
__device__ float g_k [8 * 8 * 1024 * 64];   // [B,H,T,D]
__device__ float g_v [8 * 8 * 1024 * 64];   // [B,H,T,D]
__device__ float g_p [8 * 2047 * 64];       // [H,P,D]
__device__ float g_att[8 * 1024 * 512];     // [B*T, F]

__device__ __forceinline__ void mma8(float c[4], const uint32_t a[4],
                                     uint32_t b0, uint32_t b1) {
    asm volatile(
        "mma.sync.aligned.m16n8k8.row.col.f32.tf32.tf32.f32 "
        "{%0,%1,%2,%3},{%4,%5,%6,%7},{%8,%9},{%0,%1,%2,%3};"
        : "+f"(c[0]), "+f"(c[1]), "+f"(c[2]), "+f"(c[3])
        : "r"(a[0]), "r"(a[1]), "r"(a[2]), "r"(a[3]), "r"(b0), "r"(b1));
}

// ---------------------------------------------------------------------------
// TF32 NT GEMM core: C[m,n] = sum_k A[m,k]*W[n,k]. N=K=512.
// Block tile 128x64, BK=32, register-prefetch double buffering.
// Raw fp32 bits fed to tf32 mma (hw truncation); STS.128 staging.
// 256 threads = 8 warps (4m x 2n), warp tile 32x32.
// ---------------------------------------------------------------------------
#define AST 36

__device__ __forceinline__ void gemm_core(
    const float* __restrict__ A, const float* __restrict__ W, int M,
    int m0, int n0, uint32_t* As, uint32_t* Ws, float acc[2][4][4])
{
    const int tid = threadIdx.x;
    const int warp = tid >> 5, lane = tid & 31;
    const int gid = lane >> 2, tig = lane & 3;
    const int wm = warp & 3, wn = warp >> 2;

#pragma unroll
    for (int mt = 0; mt < 2; mt++)
#pragma unroll
        for (int nt = 0; nt < 4; nt++)
#pragma unroll
            for (int i = 0; i < 4; i++) acc[mt][nt][i] = 0.f;

    float4 pa[4], pw[2];

    // Prefetch k0 = 0
#pragma unroll
    for (int r = 0; r < 4; r++) {
        int ch = tid + r * 256;
        int row = ch >> 3, c4 = (ch & 7) << 2;
        int gm = m0 + row;
        pa[r] = (gm < M) ? *(const float4*)(A + (size_t)gm * 512 + c4)
                         : make_float4(0.f, 0.f, 0.f, 0.f);
    }
#pragma unroll
    for (int r = 0; r < 2; r++) {
        int ch = tid + r * 256;
        int row = ch >> 3, c4 = (ch & 7) << 2;
        pw[r] = *(const float4*)(W + (size_t)(n0 + row) * 512 + c4);
    }

    for (int it = 0; it < 16; it++) {
        // Commit prefetched tile to smem (raw bits, one STS.128 each)
#pragma unroll
        for (int r = 0; r < 4; r++) {
            int ch = tid + r * 256;
            int row = ch >> 3, c4 = (ch & 7) << 2;
            *(float4*)&As[row * AST + c4] = pa[r];
        }
#pragma unroll
        for (int r = 0; r < 2; r++) {
            int ch = tid + r * 256;
            int row = ch >> 3, c4 = (ch & 7) << 2;
            *(float4*)&Ws[row * AST + c4] = pw[r];
        }
        __syncthreads();

        // Prefetch next tile into registers (latency overlapped with mma)
        if (it + 1 < 16) {
            int k0 = (it + 1) * 32;
#pragma unroll
            for (int r = 0; r < 4; r++) {
                int ch = tid + r * 256;
                int row = ch >> 3, c4 = (ch & 7) << 2;
                int gm = m0 + row;
                pa[r] = (gm < M)
                    ? *(const float4*)(A + (size_t)gm * 512 + k0 + c4)
                    : make_float4(0.f, 0.f, 0.f, 0.f);
            }
#pragma unroll
            for (int r = 0; r < 2; r++) {
                int ch = tid + r * 256;
                int row = ch >> 3, c4 = (ch & 7) << 2;
                pw[r] = *(const float4*)(W + (size_t)(n0 + row) * 512 + k0 + c4);
            }
        }

        // Compute current tile from smem
#pragma unroll
        for (int ks = 0; ks < 4; ks++) {
            uint32_t a[2][4];
#pragma unroll
            for (int mt = 0; mt < 2; mt++) {
                int rb = wm * 32 + mt * 16 + gid, cb = ks * 8 + tig;
                a[mt][0] = As[rb * AST + cb];
                a[mt][1] = As[(rb + 8) * AST + cb];
                a[mt][2] = As[rb * AST + cb + 4];
                a[mt][3] = As[(rb + 8) * AST + cb + 4];
            }
#pragma unroll
            for (int nt = 0; nt < 4; nt++) {
                int nb = wn * 32 + nt * 8 + gid;
                uint32_t b0 = Ws[nb * AST + ks * 8 + tig];
                uint32_t b1 = Ws[nb * AST + ks * 8 + tig + 4];
                mma8(acc[0][nt], a[0], b0, b1);
                mma8(acc[1][nt], a[1], b0, b1);
            }
        }
        __syncthreads();
    }
}

// Fused Q/K/V/P projection GEMM. blockIdx.z selects operand set.
__global__ __launch_bounds__(256) void gemm_fused(
    const float* __restrict__ query, const float* __restrict__ key,
    const float* __restrict__ value, const float* __restrict__ pos,
    const float* __restrict__ Wq, const float* __restrict__ Wk,
    const float* __restrict__ Wv, const float* __restrict__ Wp,
    const float* __restrict__ bq, const float* __restrict__ bk,
    const float* __restrict__ bvb, const float* __restrict__ bu,
    const float* __restrict__ bvv,
    float* __restrict__ o_qu, float* __restrict__ o_qv,
    float* __restrict__ o_k, float* __restrict__ o_v,
    float* __restrict__ o_p)
{
    __shared__ __align__(16) uint32_t As[128 * AST];
    __shared__ __align__(16) uint32_t Ws[64 * AST];

    const int z = blockIdx.z;
    const float *A, *W;
    int M;
    if (z == 0)      { A = query; W = Wq; M = 8192; }
    else if (z == 1) { A = key;   W = Wk; M = 8192; }
    else if (z == 2) { A = value; W = Wv; M = 8192; }
    else             { A = pos;   W = Wp; M = 2047; }

    const int m0 = blockIdx.y * 128, n0 = blockIdx.x * 64;
    if (m0 >= M) return;

    float acc[2][4][4];
    gemm_core(A, W, M, m0, n0, As, Ws, acc);

    const int tid = threadIdx.x;
    const int warp = tid >> 5, lane = tid & 31;
    const int gid = lane >> 2, tig = lane & 3;
    const int wm = warp & 3, wn = warp >> 2;
    const float scale = 0.125f;

#pragma unroll
    for (int mt = 0; mt < 2; mt++) {
#pragma unroll
        for (int hh = 0; hh < 2; hh++) {
            int m = m0 + wm * 32 + mt * 16 + gid + 8 * hh;
            if (m >= M) continue;
#pragma unroll
            for (int nt = 0; nt < 4; nt++) {
#pragma unroll
                for (int cc = 0; cc < 2; cc++) {
                    int n = n0 + wn * 32 + nt * 8 + 2 * tig + cc;
                    float v = acc[mt][nt][2 * hh + cc];
                    if (z == 0) {
                        int b = m >> 10, t = m & 1023, h = n >> 6, d = n & 63;
                        size_t idx = (((size_t)(b * 8 + h) << 10) + t) * 64 + d;
                        float base = v + bq[n];
                        o_qu[idx] = (base + bu[n]) * scale;
                        o_qv[idx] = (base + bvv[n]) * scale;
                    } else if (z == 1) {
                        int b = m >> 10, t = m & 1023, h = n >> 6, d = n & 63;
                        o_k[(((size_t)(b * 8 + h) << 10) + t) * 64 + d] =
                            v + bk[n];
                    } else if (z == 2) {
                        int b = m >> 10, t = m & 1023, h = n >> 6, d = n & 63;
                        o_v[(((size_t)(b * 8 + h) << 10) + t) * 64 + d] =
                            v + bvb[n];
                    } else {
                        int h = n >> 6, d = n & 63;
                        o_p[((size_t)h * 2047 + m) * 64 + d] = v;
                    }
                }
            }
        }
    }
}

// Output projection GEMM: d_out = att @ Wo^T + bo.
__global__ __launch_bounds__(256) void gemm_out(
    const float* __restrict__ A, const float* __restrict__ W,
    const float* __restrict__ bias, float* __restrict__ out)
{
    __shared__ __align__(16) uint32_t As[128 * AST];
    __shared__ __align__(16) uint32_t Ws[64 * AST];

    const int m0 = blockIdx.y * 128, n0 = blockIdx.x * 64;
    float acc[2][4][4];
    gemm_core(A, W, 8192, m0, n0, As, Ws, acc);

    const int tid = threadIdx.x;
    const int warp = tid >> 5, lane = tid & 31;
    const int gid = lane >> 2, tig = lane & 3;
    const int wm = warp & 3, wn = warp >> 2;

#pragma unroll
    for (int mt = 0; mt < 2; mt++)
#pragma unroll
        for (int hh = 0; hh < 2; hh++) {
            int m = m0 + wm * 32 + mt * 16 + gid + 8 * hh;
#pragma unroll
            for (int nt = 0; nt < 4; nt++)
#pragma unroll
                for (int cc = 0; cc < 2; cc++) {
                    int n = n0 + wn * 32 + nt * 8 + 2 * tig + cc;
                    out[(size_t)m * 512 + n] = acc[mt][nt][2 * hh + cc] + bias[n];
                }
        }
}

// ---------------------------------------------------------------------------
// Tensor-core flash attention with relative positions.
// scores[i,j] = qu[i]·k[j] + comp[i][j], comp[i][j] = (Qv·P_slab^T)[i][63+j-i]
// E computed over band n-tiles only, written compacted (warp-local rows).
// Raw fp32 bits to tf32 mma; STS.128 staging (no cvt). smem 87KB, 2 CTAs/SM.
// Block = 64 queries of one (b,h); 128 threads = 4 warps.
// ---------------------------------------------------------------------------
#define QST 68
#define ATT_SMEM_U32 (2 * 64 * QST + 128 * QST + 64 * QST)
#define ATT_SMEM_BYTES (ATT_SMEM_U32 * 4)

__global__ __launch_bounds__(128) void attn_mma(
    const float* __restrict__ qu, const float* __restrict__ qv,
    const float* __restrict__ kk, const float* __restrict__ vv,
    const float* __restrict__ pp, float* __restrict__ att)
{
    extern __shared__ __align__(16) uint32_t sh[];
    uint32_t* Ks = sh;                       // Qu staging, then K / exp(S)
    uint32_t* Vs = sh + 64 * QST;            // Qv staging, then V
    uint32_t* Ps = sh + 2 * 64 * QST;        // 128-row P slab
    float*    Cp = (float*)(sh + 2 * 64 * QST + 128 * QST);  // 64x68 band

    const int tid = threadIdx.x;
    const int w = tid >> 5, lane = tid & 31;
    const int gid = lane >> 2, tig = lane & 3;
    const int i0 = blockIdx.x << 6;
    const int bh = blockIdx.y;
    const int h = bh & 7, b = bh >> 3;

    // Stage Q tiles (raw bits) into the K/V buffers, extract frags, release.
#pragma unroll
    for (int r = 0; r < 8; r++) {
        int fi = tid + r * 128;
        int row = fi >> 4, c4 = (fi & 15) << 2;
        size_t g = ((size_t)bh * 1024 + i0 + row) * 64 + c4;
        *(float4*)&Ks[row * QST + c4] = *(const float4*)(qu + g);
        *(float4*)&Vs[row * QST + c4] = *(const float4*)(qv + g);
    }
    __syncthreads();

    uint32_t qua[8][4], qva[8][4];
#pragma unroll
    for (int ks = 0; ks < 8; ks++) {
        int rb = w * 16 + gid, cb = ks * 8 + tig;
        qua[ks][0] = Ks[rb * QST + cb];
        qua[ks][1] = Ks[(rb + 8) * QST + cb];
        qua[ks][2] = Ks[rb * QST + cb + 4];
        qua[ks][3] = Ks[(rb + 8) * QST + cb + 4];
        qva[ks][0] = Vs[rb * QST + cb];
        qva[ks][1] = Vs[(rb + 8) * QST + cb];
        qva[ks][2] = Vs[rb * QST + cb + 4];
        qva[ks][3] = Vs[(rb + 8) * QST + cb + 4];
    }

    float m_i[2] = {-1e30f, -1e30f}, l_i[2] = {0.f, 0.f};
    float oC[8][4];
#pragma unroll
    for (int nt = 0; nt < 8; nt++)
#pragma unroll
        for (int i = 0; i < 4; i++) oC[nt][i] = 0.f;

    // E band window for this warp's 16 rows: cols [48-16w, 126-16w]
    const int lo = 48 - w * 16, hi = 126 - w * 16;

    for (int jt = 0; jt < 16; jt++) {
        const int j0 = jt << 6;
        __syncthreads();   // prior iteration (and Q staging) done with smem

        // Stage K, V tiles (raw bits, STS.128)
#pragma unroll
        for (int r = 0; r < 8; r++) {
            int fi = tid + r * 128;
            int row = fi >> 4, c4 = (fi & 15) << 2;
            size_t g = ((size_t)bh * 1024 + j0 + row) * 64 + c4;
            *(float4*)&Ks[row * QST + c4] = *(const float4*)(kk + g);
            *(float4*)&Vs[row * QST + c4] = *(const float4*)(vv + g);
        }
        // Stage P slab rows rbase..rbase+127 (row 127 pads an unused E col)
        const int rbase = 960 + j0 - i0;
#pragma unroll
        for (int r = 0; r < 16; r++) {
            int fi = tid + r * 128;
            int row = fi >> 4, c4 = (fi & 15) << 2;
            int prow = rbase + row;
            prow = prow > 2046 ? 2046 : prow;
            *(float4*)&Ps[row * QST + c4] =
                *(const float4*)(pp + ((size_t)h * 2047 + prow) * 64 + c4);
        }
        __syncthreads();

        // E = Qv @ P_slab^T over band n-tiles only; write compacted.
#pragma unroll
        for (int nt = 0; nt < 16; nt++) {
            if (nt * 8 + 7 < lo || nt * 8 > hi) continue;
            float e[4] = {0.f, 0.f, 0.f, 0.f};
#pragma unroll
            for (int ks = 0; ks < 8; ks++) {
                int rb = nt * 8 + gid, cb = ks * 8 + tig;
                mma8(e, qva[ks], Ps[rb * QST + cb], Ps[rb * QST + cb + 4]);
            }
            int er = w * 16 + gid, ec = nt * 8 + 2 * tig;
#pragma unroll
            for (int hh = 0; hh < 2; hh++) {
#pragma unroll
                for (int cc = 0; cc < 2; cc++) {
                    int row = er + 8 * hh;
                    int col = ec + cc - 63 + row;   // j index
                    if (col >= 0 && col < 64)
                        Cp[row * QST + col] = e[2 * hh + cc];
                }
            }
        }

        // S1 = Qu @ K^T
        float sC[8][4];
#pragma unroll
        for (int nt = 0; nt < 8; nt++)
#pragma unroll
            for (int i = 0; i < 4; i++) sC[nt][i] = 0.f;
#pragma unroll
        for (int ks = 0; ks < 8; ks++) {
#pragma unroll
            for (int nt = 0; nt < 8; nt++) {
                int rb = nt * 8 + gid, cb = ks * 8 + tig;
                mma8(sC[nt], qua[ks], Ks[rb * QST + cb], Ks[rb * QST + cb + 4]);
            }
        }
        __syncthreads();   // all warps done reading Ks before exp overwrite

        // Online softmax; write exp(S) raw bits into own warp's Ks rows
#pragma unroll
        for (int hh = 0; hh < 2; hh++) {
            int qrow = w * 16 + gid + 8 * hh;
            float sv[16];
            float mx = -1e30f;
#pragma unroll
            for (int nt = 0; nt < 8; nt++) {
#pragma unroll
                for (int cc = 0; cc < 2; cc++) {
                    int jl = nt * 8 + 2 * tig + cc;
                    float s = sC[nt][2 * hh + cc] + Cp[qrow * QST + jl];
                    sv[nt * 2 + cc] = s;
                    mx = fmaxf(mx, s);
                }
            }
            mx = fmaxf(mx, __shfl_xor_sync(0xffffffffu, mx, 1));
            mx = fmaxf(mx, __shfl_xor_sync(0xffffffffu, mx, 2));
            float mn = fmaxf(m_i[hh], mx);
            float al = __expf(m_i[hh] - mn);
            float rs = 0.f;
#pragma unroll
            for (int t = 0; t < 16; t++) {
                float p = __expf(sv[t] - mn);
                rs += p;
                int nt = t >> 1, cc = t & 1;
                int jl = nt * 8 + 2 * tig + cc;
                Ks[qrow * QST + jl] = __float_as_uint(p);
            }
            rs += __shfl_xor_sync(0xffffffffu, rs, 1);
            rs += __shfl_xor_sync(0xffffffffu, rs, 2);
            l_i[hh] = l_i[hh] * al + rs;
            m_i[hh] = mn;
#pragma unroll
            for (int nt = 0; nt < 8; nt++) {
                oC[nt][2 * hh] *= al;
                oC[nt][2 * hh + 1] *= al;
            }
        }
        __syncwarp();   // exp tile rows are warp-local

        // O += exp(S) @ V
#pragma unroll
        for (int ks = 0; ks < 8; ks++) {
            uint32_t a[4];
            int rb = w * 16 + gid, cb = ks * 8 + tig;
            a[0] = Ks[rb * QST + cb];
            a[1] = Ks[(rb + 8) * QST + cb];
            a[2] = Ks[rb * QST + cb + 4];
            a[3] = Ks[(rb + 8) * QST + cb + 4];
#pragma unroll
            for (int nt = 0; nt < 8; nt++) {
                uint32_t b0 = Vs[(ks * 8 + tig) * QST + nt * 8 + gid];
                uint32_t b1 = Vs[(ks * 8 + tig + 4) * QST + nt * 8 + gid];
                mma8(oC[nt], a, b0, b1);
            }
        }
    }

    // Write normalized output: att[b, t, h*64+d]
#pragma unroll
    for (int hh = 0; hh < 2; hh++) {
        int t = i0 + w * 16 + gid + 8 * hh;
        float inv = 1.f / l_i[hh];
#pragma unroll
        for (int nt = 0; nt < 8; nt++) {
            int d = nt * 8 + 2 * tig;
            size_t o = (((size_t)b * 1024 + t) * 8 + h) * 64 + d;
            att[o]     = oC[nt][2 * hh] * inv;
            att[o + 1] = oC[nt][2 * hh + 1] * inv;
        }
    }
}

// ---------------------------------------------------------------------------
extern "C" void kernel_launch(void* const* d_in, const int* in_sizes, int n_in,
                              void* d_out, int out_size)
{
    const float* query = (const float*)d_in[0];
    const float* key   = (const float*)d_in[1];
    const float* value = (const float*)d_in[2];
    const float* pos   = (const float*)d_in[3];
    const float* Wq    = (const float*)d_in[4];
    const float* bq    = (const float*)d_in[5];
    const float* Wk    = (const float*)d_in[6];
    const float* bk    = (const float*)d_in[7];
    const float* Wv    = (const float*)d_in[8];
    const float* bv_   = (const float*)d_in[9];
    const float* Wp    = (const float*)d_in[10];
    const float* Wo    = (const float*)d_in[11];
    const float* bo    = (const float*)d_in[12];
    const float* pbu   = (const float*)d_in[13];
    const float* pbv   = (const float*)d_in[14];

    float *qu_p, *qv_p, *k_p, *v_p, *p_p, *att_p;
    cudaGetSymbolAddress((void**)&qu_p,  g_qu);
    cudaGetSymbolAddress((void**)&qv_p,  g_qv);
    cudaGetSymbolAddress((void**)&k_p,   g_k);
    cudaGetSymbolAddress((void**)&v_p,   g_v);
    cudaGetSymbolAddress((void**)&p_p,   g_p);
    cudaGetSymbolAddress((void**)&att_p, g_att);

    cudaFuncSetAttribute(attn_mma,
                         cudaFuncAttributeMaxDynamicSharedMemorySize,
                         ATT_SMEM_BYTES);

    gemm_fused<<<dim3(8, 64, 4), 256>>>(
        query, key, value, pos, Wq, Wk, Wv, Wp,
        bq, bk, bv_, pbu, pbv,
        qu_p, qv_p, k_p, v_p, p_p);

    attn_mma<<<dim3(16, 64), dim3(128), ATT_SMEM_BYTES>>>(qu_p, qv_p, k_p, v_p,
                                                          p_p, att_p);

    gemm_out<<<dim3(8, 64), 256>>>(att_p, Wo, bo, (float*)d_out);
}